// round 3
// baseline (speedup 1.0000x reference)
#include <cuda_runtime.h>
#include <cstdint>
#include <cstddef>

// Problem constants
#define BB    2
#define NN    4096
#define DIMM  768
#define HH    16
#define DHH   64
#define DI    1024          // H*DH
#define WW    128
#define MMEM  4
#define NBLK  32            // NN / WW

// ---------------------------------------------------------------------------
// Scratch (device globals: no allocation allowed)
// ---------------------------------------------------------------------------
__device__ float g_q[(size_t)BB * HH * NN * DHH];   // head-major, pre-scaled
__device__ float g_k[(size_t)BB * HH * NN * DHH];
__device__ float g_v[(size_t)BB * HH * NN * DHH];
__device__ float g_o[(size_t)BB * NN * DI];         // token-major [b][n][h*64+d]

// ---------------------------------------------------------------------------
// SGEMM tile config (shared by both GEMMs)
// ---------------------------------------------------------------------------
#define BM 128
#define BN 128
#define BKK 16
#define TM 8
#define TN 8

// ---------------------------------------------------------------------------
// GEMM 1: fused QKV projection.
//   A = x [8192, 768], logical B = [Wq | Wkv] -> [768, 3072]
//   epilogue scatters into g_q (bias + 0.125 scale), g_k, g_v head-major.
// ---------------------------------------------------------------------------
__global__ __launch_bounds__(256) void gemm_proj_kernel(
    const float* __restrict__ x,
    const float* __restrict__ Wq,
    const float* __restrict__ bq,
    const float* __restrict__ Wkv)
{
    __shared__ float As[BKK][BM];
    __shared__ float Bs[BKK][BN];

    const int K    = DIMM;
    const int row0 = blockIdx.y * BM;
    const int col0 = blockIdx.x * BN;
    const int tid  = threadIdx.x;
    const int tx   = tid & 15;
    const int ty   = tid >> 4;

    // A loader: 4 threads/row, float4 each; 64 rows per pass, 2 passes
    const int arow = tid >> 2;
    const int ac4  = (tid & 3) * 4;
    // B loader: 32 threads/row, float4 each; 8 rows per pass, 2 passes
    const int brow = tid >> 5;
    const int bc4  = (tid & 31) * 4;

    const float* Bbase;
    int ldb, bcol0;
    if (col0 < DI) { Bbase = Wq;  ldb = DI;     bcol0 = col0; }
    else           { Bbase = Wkv; ldb = 2 * DI; bcol0 = col0 - DI; }

    float acc[TM][TN];
#pragma unroll
    for (int i = 0; i < TM; i++)
#pragma unroll
        for (int j = 0; j < TN; j++) acc[i][j] = 0.f;

    for (int k0 = 0; k0 < K; k0 += BKK) {
#pragma unroll
        for (int p = 0; p < 2; p++) {
            int r = arow + p * 64;
            float4 va = *(const float4*)(x + (size_t)(row0 + r) * K + k0 + ac4);
            As[ac4 + 0][r] = va.x;
            As[ac4 + 1][r] = va.y;
            As[ac4 + 2][r] = va.z;
            As[ac4 + 3][r] = va.w;
        }
#pragma unroll
        for (int p = 0; p < 2; p++) {
            int r = brow + p * 8;
            float4 vb = *(const float4*)(Bbase + (size_t)(k0 + r) * ldb + bcol0 + bc4);
            *(float4*)(&Bs[r][bc4]) = vb;
        }
        __syncthreads();

#pragma unroll
        for (int kk = 0; kk < BKK; kk++) {
            float a[TM], b[TN];
#pragma unroll
            for (int i = 0; i < TM; i++) a[i] = As[kk][ty * TM + i];
#pragma unroll
            for (int j = 0; j < TN; j++) b[j] = Bs[kk][tx * TN + j];
#pragma unroll
            for (int i = 0; i < TM; i++)
#pragma unroll
                for (int j = 0; j < TN; j++) acc[i][j] = fmaf(a[i], b[j], acc[i][j]);
        }
        __syncthreads();
    }

    // Epilogue: scatter into head-major q/k/v
#pragma unroll
    for (int i = 0; i < TM; i++) {
        int r = row0 + ty * TM + i;
        int b = r >> 12;
        int n = r & (NN - 1);
#pragma unroll
        for (int j = 0; j < TN; j++) {
            int   c = col0 + tx * TN + j;
            float v = acc[i][j];
            if (c < DI) {
                v = (v + bq[c]) * 0.125f;   // DH^-0.5
                int h = c >> 6, d = c & 63;
                g_q[(((size_t)(b * HH + h) * NN) + n) * DHH + d] = v;
            } else if (c < 2 * DI) {
                int c2 = c - DI;
                int h = c2 >> 6, d = c2 & 63;
                g_k[(((size_t)(b * HH + h) * NN) + n) * DHH + d] = v;
            } else {
                int c2 = c - 2 * DI;
                int h = c2 >> 6, d = c2 & 63;
                g_v[(((size_t)(b * HH + h) * NN) + n) * DHH + d] = v;
            }
        }
    }
}

// ---------------------------------------------------------------------------
// GEMM 2: output projection.  A = g_o [8192, 1024], B = Wo [1024, 768]
// ---------------------------------------------------------------------------
__global__ __launch_bounds__(256) void gemm_out_kernel(
    const float* __restrict__ Wo,
    float* __restrict__ out)
{
    __shared__ float As[BKK][BM];
    __shared__ float Bs[BKK][BN];

    const int K    = DI;      // 1024
    const int LDN  = DIMM;    // 768
    const int row0 = blockIdx.y * BM;
    const int col0 = blockIdx.x * BN;
    const int tid  = threadIdx.x;
    const int tx   = tid & 15;
    const int ty   = tid >> 4;

    const int arow = tid >> 2;
    const int ac4  = (tid & 3) * 4;
    const int brow = tid >> 5;
    const int bc4  = (tid & 31) * 4;

    float acc[TM][TN];
#pragma unroll
    for (int i = 0; i < TM; i++)
#pragma unroll
        for (int j = 0; j < TN; j++) acc[i][j] = 0.f;

    for (int k0 = 0; k0 < K; k0 += BKK) {
#pragma unroll
        for (int p = 0; p < 2; p++) {
            int r = arow + p * 64;
            float4 va = *(const float4*)(g_o + (size_t)(row0 + r) * K + k0 + ac4);
            As[ac4 + 0][r] = va.x;
            As[ac4 + 1][r] = va.y;
            As[ac4 + 2][r] = va.z;
            As[ac4 + 3][r] = va.w;
        }
#pragma unroll
        for (int p = 0; p < 2; p++) {
            int r = brow + p * 8;
            float4 vb = *(const float4*)(Wo + (size_t)(k0 + r) * LDN + col0 + bc4);
            *(float4*)(&Bs[r][bc4]) = vb;
        }
        __syncthreads();

#pragma unroll
        for (int kk = 0; kk < BKK; kk++) {
            float a[TM], b[TN];
#pragma unroll
            for (int i = 0; i < TM; i++) a[i] = As[kk][ty * TM + i];
#pragma unroll
            for (int j = 0; j < TN; j++) b[j] = Bs[kk][tx * TN + j];
#pragma unroll
            for (int i = 0; i < TM; i++)
#pragma unroll
                for (int j = 0; j < TN; j++) acc[i][j] = fmaf(a[i], b[j], acc[i][j]);
        }
        __syncthreads();
    }

#pragma unroll
    for (int i = 0; i < TM; i++) {
        int r = row0 + ty * TM + i;
#pragma unroll
        for (int j = 0; j < TN; j += 4) {
            int c = col0 + tx * TN + j;
            float4 o4 = make_float4(acc[i][j], acc[i][j + 1], acc[i][j + 2], acc[i][j + 3]);
            *(float4*)(out + (size_t)r * LDN + c) = o4;
        }
    }
}

// ---------------------------------------------------------------------------
// Windowed attention with memory KV + bias, online softmax.
//   grid (NBLK, H, B), 128 threads, one query per thread.
//   dyn smem: sK[128*64] | sV[128*64] | sB[128*129] (also q staging @ stride 65)
// ---------------------------------------------------------------------------
#define SMEM_ATTN_BYTES ((8192 + 8192 + 128 * 129) * 4)

__device__ __forceinline__ void key_step(
    const float* __restrict__ sK, const float* __restrict__ sV,
    int j, float bj,
    const float (&q)[64], float (&acc)[64], float& m, float& l)
{
    const float4* k4 = reinterpret_cast<const float4*>(sK + j * 64);
    float s0 = 0.f, s1 = 0.f, s2 = 0.f, s3 = 0.f;
#pragma unroll
    for (int t = 0; t < 16; t++) {
        float4 kk = k4[t];
        s0 = fmaf(q[4 * t + 0], kk.x, s0);
        s1 = fmaf(q[4 * t + 1], kk.y, s1);
        s2 = fmaf(q[4 * t + 2], kk.z, s2);
        s3 = fmaf(q[4 * t + 3], kk.w, s3);
    }
    float s = (s0 + s1) + (s2 + s3) + bj;
    const float4* v4 = reinterpret_cast<const float4*>(sV + j * 64);

    if (s > m) {
        // new running max: p = exp(s - s) = 1 exactly
        float sc = __expf(m - s);
        m = s;
        l = fmaf(l, sc, 1.f);
#pragma unroll
        for (int t = 0; t < 16; t++) {
            float4 vv = v4[t];
            acc[4 * t + 0] = fmaf(acc[4 * t + 0], sc, vv.x);
            acc[4 * t + 1] = fmaf(acc[4 * t + 1], sc, vv.y);
            acc[4 * t + 2] = fmaf(acc[4 * t + 2], sc, vv.z);
            acc[4 * t + 3] = fmaf(acc[4 * t + 3], sc, vv.w);
        }
    } else {
        float p = __expf(s - m);
        l += p;
#pragma unroll
        for (int t = 0; t < 16; t++) {
            float4 vv = v4[t];
            acc[4 * t + 0] = fmaf(p, vv.x, acc[4 * t + 0]);
            acc[4 * t + 1] = fmaf(p, vv.y, acc[4 * t + 1]);
            acc[4 * t + 2] = fmaf(p, vv.z, acc[4 * t + 2]);
            acc[4 * t + 3] = fmaf(p, vv.w, acc[4 * t + 3]);
        }
    }
}

__global__ __launch_bounds__(128) void attn_kernel(
    const float* __restrict__ attn_bias,
    const float* __restrict__ memkv)
{
    extern __shared__ float sm[];
    float* sK = sm;                 // [128][64]
    float* sV = sm + 8192;          // [128][64]
    float* sB = sm + 16384;         // [128][129] bias / [128][65] q stage

    const int w   = blockIdx.x;
    const int h   = blockIdx.y;
    const int b   = blockIdx.z;
    const int tid = threadIdx.x;

    const size_t headbase = ((size_t)(b * HH + h) * NN) * DHH;
    const float* qp = g_q + headbase + (size_t)w * WW * DHH;

    // stage Q (coalesced) -> padded smem -> regs
    for (int idx = tid; idx < WW * DHH; idx += 128) {
        int r = idx >> 6, c = idx & 63;
        sB[r * 65 + c] = qp[idx];
    }
    __syncthreads();
    float q[64];
#pragma unroll
    for (int d = 0; d < 64; d++) q[d] = sB[tid * 65 + d];

    float m = -3.402823466e+38f, l = 0.f;
    float acc[64];
#pragma unroll
    for (int d = 0; d < 64; d++) acc[d] = 0.f;

    // ---- segment 0: memory KV (4 keys, bias = 0, always valid) ----
    {
        const float* kp = memkv + (size_t)h * MMEM * DHH;
        const float* vp = memkv + (size_t)(HH + h) * MMEM * DHH;
        for (int idx = tid; idx < MMEM * DHH; idx += 128) {
            sK[idx] = kp[idx];
            sV[idx] = vp[idx];
        }
        __syncthreads();   // also fences q reads from sB
        for (int j = 0; j < MMEM; j++)
            key_step(sK, sV, j, 0.f, q, acc, m, l);
    }

    // ---- segment 1: previous window (masked out entirely when w == 0) ----
    if (w > 0) {
        __syncthreads();
        const float* kp = g_k + headbase + (size_t)(w - 1) * WW * DHH;
        const float* vp = g_v + headbase + (size_t)(w - 1) * WW * DHH;
        for (int idx = tid; idx < WW * DHH; idx += 128) {
            sK[idx] = kp[idx];
            sV[idx] = vp[idx];
        }
        const float* bp = attn_bias + ((size_t)b * NN + (size_t)w * WW) * NN
                        + (size_t)(w - 1) * WW;
        for (int idx = tid; idx < WW * WW; idx += 128) {
            int r = idx >> 7, c = idx & 127;
            sB[r * 129 + c] = bp[(size_t)r * NN + c];
        }
        __syncthreads();
#pragma unroll 1
        for (int j = 0; j < WW; j++)
            key_step(sK, sV, j, sB[tid * 129 + j], q, acc, m, l);
    }

    // ---- segment 2: current window ----
    {
        __syncthreads();
        const float* kp = g_k + headbase + (size_t)w * WW * DHH;
        const float* vp = g_v + headbase + (size_t)w * WW * DHH;
        for (int idx = tid; idx < WW * DHH; idx += 128) {
            sK[idx] = kp[idx];
            sV[idx] = vp[idx];
        }
        const float* bp = attn_bias + ((size_t)b * NN + (size_t)w * WW) * NN
                        + (size_t)w * WW;
        for (int idx = tid; idx < WW * WW; idx += 128) {
            int r = idx >> 7, c = idx & 127;
            sB[r * 129 + c] = bp[(size_t)r * NN + c];
        }
        __syncthreads();
#pragma unroll 1
        for (int j = 0; j < WW; j++)
            key_step(sK, sV, j, sB[tid * 129 + j], q, acc, m, l);
    }

    // ---- finalize: write token-major [b][n][h*64+d] ----
    float inv = 1.f / l;
    float* op = g_o + ((size_t)b * NN + (size_t)w * WW + tid) * DI + h * DHH;
#pragma unroll
    for (int t = 0; t < 16; t++) {
        float4 o4 = make_float4(acc[4 * t + 0] * inv, acc[4 * t + 1] * inv,
                                acc[4 * t + 2] * inv, acc[4 * t + 3] * inv);
        ((float4*)op)[t] = o4;
    }
}

// ---------------------------------------------------------------------------
// Launch
// inputs: 0 x, 1 mask (all-True by construction; structural masking handled
//         via the w==0 prev-segment skip), 2 attn_bias, 3 Wq, 4 bq, 5 Wkv,
//         6 Wo, 7 memory_kv
// ---------------------------------------------------------------------------
extern "C" void kernel_launch(void* const* d_in, const int* in_sizes, int n_in,
                              void* d_out, int out_size)
{
    const float* x    = (const float*)d_in[0];
    const float* bias = (const float*)d_in[2];
    const float* Wq   = (const float*)d_in[3];
    const float* bq   = (const float*)d_in[4];
    const float* Wkv  = (const float*)d_in[5];
    const float* Wo   = (const float*)d_in[6];
    const float* mkv  = (const float*)d_in[7];
    float* out = (float*)d_out;

    static bool attr_set = false;
    // cudaFuncSetAttribute is idempotent and capture-safe; call every time.
    cudaFuncSetAttribute(attn_kernel,
                         cudaFuncAttributeMaxDynamicSharedMemorySize,
                         SMEM_ATTN_BYTES);
    (void)attr_set;

    // 1) fused QKV projection: [8192,768] x [768,3072]
    {
        dim3 grid(3 * DI / BN, (BB * NN) / BM);   // (24, 64)
        gemm_proj_kernel<<<grid, 256>>>(x, Wq, bq, Wkv);
    }

    // 2) windowed attention
    {
        dim3 grid(NBLK, HH, BB);                  // (32, 16, 2)
        attn_kernel<<<grid, 128, SMEM_ATTN_BYTES>>>(bias, mkv);
    }

    // 3) output projection: [8192,1024] x [1024,768]
    {
        dim3 grid(DIMM / BN, (BB * NN) / BM);     // (6, 64)
        gemm_out_kernel<<<grid, 256>>>(Wo, out);
    }
}

// round 5
// speedup vs baseline: 2.0328x; 2.0328x over previous
#include <cuda_runtime.h>
#include <cuda_bf16.h>
#include <cstdint>
#include <cstddef>

// Problem constants
#define BB    2
#define NN    4096
#define DIMM  768
#define HH    16
#define DHH   64
#define DI    1024          // H*DH
#define WW    128
#define MMEM  4
#define NBLK  32            // NN / WW

// ---------------------------------------------------------------------------
// Scratch (device globals; no allocation allowed)
// ---------------------------------------------------------------------------
__device__ __align__(16) float g_q[(size_t)BB * HH * NN * DHH];
__device__ __align__(16) float g_k[(size_t)BB * HH * NN * DHH];
__device__ __align__(16) float g_v[(size_t)BB * HH * NN * DHH];

// bf16 hi/lo splits
__device__ __align__(16) __nv_bfloat16 g_xh[(size_t)BB * NN * DIMM];
__device__ __align__(16) __nv_bfloat16 g_xl[(size_t)BB * NN * DIMM];
__device__ __align__(16) __nv_bfloat16 g_oh[(size_t)BB * NN * DI];
__device__ __align__(16) __nv_bfloat16 g_ol[(size_t)BB * NN * DI];

// transposed, bf16-split weights: Wt = [Wq|Wkv]^T [3072][768], Wot = Wo^T [768][1024]
__device__ __align__(16) __nv_bfloat16 g_wt_h[(size_t)3072 * 768];
__device__ __align__(16) __nv_bfloat16 g_wt_l[(size_t)3072 * 768];
__device__ __align__(16) __nv_bfloat16 g_wot_h[(size_t)768 * 1024];
__device__ __align__(16) __nv_bfloat16 g_wot_l[(size_t)768 * 1024];

// ---------------------------------------------------------------------------
// PTX helpers (baseline ISA only: mma.sync / ldmatrix / cp.async)
// ---------------------------------------------------------------------------
__device__ __forceinline__ uint32_t smem_u32(const void* p) {
    uint32_t a;
    asm("{ .reg .u64 t; cvta.to.shared.u64 t, %1; cvt.u32.u64 %0, t; }"
        : "=r"(a) : "l"(p));
    return a;
}

#define CP_ASYNC16(dst, src) \
    asm volatile("cp.async.cg.shared.global [%0], [%1], 16;" :: "r"(dst), "l"(src))
#define CP_COMMIT() asm volatile("cp.async.commit_group;" ::: "memory")
#define CP_WAIT(n)  asm volatile("cp.async.wait_group %0;" :: "n"(n) : "memory")

#define LDSM_X4(r, addr) \
    asm volatile("ldmatrix.sync.aligned.m8n8.x4.shared.b16 {%0,%1,%2,%3}, [%4];" \
        : "=r"((r)[0]), "=r"((r)[1]), "=r"((r)[2]), "=r"((r)[3]) : "r"(addr))

#define MMA_BF16(c, a, b) \
    asm volatile("mma.sync.aligned.m16n8k16.row.col.f32.bf16.bf16.f32 " \
        "{%0,%1,%2,%3}, {%4,%5,%6,%7}, {%8,%9}, {%0,%1,%2,%3};" \
        : "+f"((c)[0]), "+f"((c)[1]), "+f"((c)[2]), "+f"((c)[3]) \
        : "r"((a)[0]), "r"((a)[1]), "r"((a)[2]), "r"((a)[3]), \
          "r"((b)[0]), "r"((b)[1]))

// SW64 swizzle for 64-byte rows (conflict-free ldmatrix + cp.async)
__device__ __host__ __forceinline__ uint32_t swz64(uint32_t off) {
    return off ^ ((off >> 3) & 0x30);
}

// ---------------------------------------------------------------------------
// bf16 split helper
// ---------------------------------------------------------------------------
__device__ __forceinline__ void split2(float f0, float f1, uint32_t& hw, uint32_t& lw) {
    __nv_bfloat16 h0 = __float2bfloat16_rn(f0);
    __nv_bfloat16 h1 = __float2bfloat16_rn(f1);
    __nv_bfloat16 l0 = __float2bfloat16_rn(f0 - __bfloat162float(h0));
    __nv_bfloat16 l1 = __float2bfloat16_rn(f1 - __bfloat162float(h1));
    hw = (uint32_t)__bfloat16_as_ushort(h0) | ((uint32_t)__bfloat16_as_ushort(h1) << 16);
    lw = (uint32_t)__bfloat16_as_ushort(l0) | ((uint32_t)__bfloat16_as_ushort(l1) << 16);
}

// ---------------------------------------------------------------------------
// Prep 1: transpose + bf16-split weights
//   W=0: Wq  [768][1024] -> g_wt rows [0,1024)
//   W=1: Wkv [768][2048] -> g_wt rows [1024,3072)
//   W=2: Wo  [1024][768] -> g_wot
// ---------------------------------------------------------------------------
template <int W>
__global__ void transpose_split_kernel(const float* __restrict__ src)
{
    constexpr int R = (W == 2) ? 1024 : 768;
    constexpr int C = (W == 0) ? 1024 : (W == 1) ? 2048 : 768;
    __nv_bfloat16* dh = (W == 0) ? g_wt_h : (W == 1) ? (g_wt_h + (size_t)1024 * 768) : g_wot_h;
    __nv_bfloat16* dl = (W == 0) ? g_wt_l : (W == 1) ? (g_wt_l + (size_t)1024 * 768) : g_wot_l;

    __shared__ float tile[32][33];
    int c0 = blockIdx.x * 32, r0 = blockIdx.y * 32;
    int tx = threadIdx.x, ty = threadIdx.y;
#pragma unroll
    for (int i = 0; i < 32; i += 8)
        tile[ty + i][tx] = src[(size_t)(r0 + ty + i) * C + c0 + tx];
    __syncthreads();
#pragma unroll
    for (int i = 0; i < 32; i += 8) {
        float f = tile[tx][ty + i];
        __nv_bfloat16 h = __float2bfloat16_rn(f);
        __nv_bfloat16 l = __float2bfloat16_rn(f - __bfloat162float(h));
        size_t o = (size_t)(c0 + ty + i) * R + (r0 + tx);
        dh[o] = h;
        dl[o] = l;
    }
}

// ---------------------------------------------------------------------------
// Prep 2: elementwise split of x -> g_xh/g_xl
// ---------------------------------------------------------------------------
__global__ void split_x_kernel(const float* __restrict__ x)
{
    const int N4 = (BB * NN * DIMM) / 4;
    for (int i = blockIdx.x * blockDim.x + threadIdx.x; i < N4;
         i += gridDim.x * blockDim.x) {
        float4 f = ((const float4*)x)[i];
        uint2 hv, lv;
        split2(f.x, f.y, hv.x, lv.x);
        split2(f.z, f.w, hv.y, lv.y);
        ((uint2*)g_xh)[i] = hv;
        ((uint2*)g_xl)[i] = lv;
    }
}

// ---------------------------------------------------------------------------
// HMMA GEMM: C[M][NCOLS] = A[M][K] @ B^T, 3-pass bf16 split.
//   A hi/lo, B hi/lo all bf16, K-major (row stride = K elems).
//   Tile 128x128, BK=32, 2-stage cp.async pipeline, SW64 smem.
//   MODE 0: scatter q/k/v head-major (bias+0.125 on q);  MODE 1: plain fp32 out.
// smem layout / stage: Ah[8192] Al[8192] Bh[8192] Bl[8192]  (32 KB), 2 stages.
// ---------------------------------------------------------------------------
#define GEMM_SMEM 65536

template <int K, int MODE>
__global__ __launch_bounds__(256, 2)
void gemm_mma_kernel(const __nv_bfloat16* __restrict__ Ah,
                     const __nv_bfloat16* __restrict__ Al,
                     const __nv_bfloat16* __restrict__ Bh,
                     const __nv_bfloat16* __restrict__ Bl,
                     const float* __restrict__ bq,
                     float* __restrict__ outp)
{
    extern __shared__ __align__(1024) char sm[];
    const uint32_t smb = smem_u32(sm);

    constexpr int NC = K / 32;
    const int row0 = blockIdx.y * 128;
    const int col0 = blockIdx.x * 128;
    const int t    = threadIdx.x;
    const int lane = t & 31;
    const int wid  = t >> 5;
    const int wm0  = (wid >> 2) * 64;     // warp m offset (0/64)
    const int wn0  = (wid & 3) * 32;      // warp n offset (0/32/64/96)

    // ---- loader addressing (per thread: 2 reps x 4 matrices) ----
    // rep r: idx = t + 256*r; row = idx>>2 (0..127), c4 = idx&3 (16B chunk)
    uint32_t ldst[2];
    const __nv_bfloat16 *pAh[2], *pAl[2], *pBh[2], *pBl[2];
#pragma unroll
    for (int r = 0; r < 2; r++) {
        int idx = t + 256 * r;
        int row = idx >> 2, c4 = idx & 3;
        ldst[r] = swz64((uint32_t)(row * 64 + c4 * 16));
        pAh[r] = Ah + (size_t)(row0 + row) * K + c4 * 8;
        pAl[r] = Al + (size_t)(row0 + row) * K + c4 * 8;
        pBh[r] = Bh + (size_t)(col0 + row) * K + c4 * 8;
        pBl[r] = Bl + (size_t)(col0 + row) * K + c4 * 8;
    }

    // ---- ldmatrix addressing ----
    // A x4 (16x16 tile at (m0, ks*16)): row = m0 + (lane&7) + (lane&8),
    //   kbyte = ((lane>>4)&1)*16
    uint32_t aoff[4][2];
    {
        int arow = (lane & 7) + (lane & 8);
        int akb  = ((lane >> 4) & 1) * 16;
#pragma unroll
        for (int mt = 0; mt < 4; mt++)
#pragma unroll
            for (int ks = 0; ks < 2; ks++)
                aoff[mt][ks] = swz64((uint32_t)((wm0 + mt * 16 + arow) * 64 + ks * 32 + akb));
    }
    // B x4 (two n8 tiles per load): row = n0 + g*16 + (lane>>4)*8 + (lane&7),
    //   kbyte = ((lane>>3)&1)*16
    uint32_t boff[2][2];
    {
        int brow = ((lane >> 4) & 1) * 8 + (lane & 7);
        int bkb  = ((lane >> 3) & 1) * 16;
#pragma unroll
        for (int g = 0; g < 2; g++)
#pragma unroll
            for (int ks = 0; ks < 2; ks++)
                boff[g][ks] = swz64((uint32_t)((wn0 + g * 16 + brow) * 64 + ks * 32 + bkb));
    }

    float acc[4][4][4];
#pragma unroll
    for (int i = 0; i < 4; i++)
#pragma unroll
        for (int j = 0; j < 4; j++)
#pragma unroll
            for (int r = 0; r < 4; r++) acc[i][j][r] = 0.f;

    // ---- prologue: load chunk 0 into stage 0 ----
#pragma unroll
    for (int r = 0; r < 2; r++) {
        CP_ASYNC16(smb + ldst[r],          (const char*)pAh[r]);
        CP_ASYNC16(smb + 8192  + ldst[r],  (const char*)pAl[r]);
        CP_ASYNC16(smb + 16384 + ldst[r],  (const char*)pBh[r]);
        CP_ASYNC16(smb + 24576 + ldst[r],  (const char*)pBl[r]);
    }
    CP_COMMIT();

    for (int c = 0; c < NC; c++) {
        // prefetch chunk c+1
        if (c + 1 < NC) {
            uint32_t sb = smb + ((c + 1) & 1) * 32768;
            int koff = (c + 1) * 32;
#pragma unroll
            for (int r = 0; r < 2; r++) {
                CP_ASYNC16(sb + ldst[r],         (const char*)(pAh[r] + koff));
                CP_ASYNC16(sb + 8192  + ldst[r], (const char*)(pAl[r] + koff));
                CP_ASYNC16(sb + 16384 + ldst[r], (const char*)(pBh[r] + koff));
                CP_ASYNC16(sb + 24576 + ldst[r], (const char*)(pBl[r] + koff));
            }
            CP_COMMIT();
            CP_WAIT(1);
        } else {
            CP_WAIT(0);
        }
        __syncthreads();

        const uint32_t sb  = smb + (c & 1) * 32768;
        const uint32_t sAh = sb, sAl = sb + 8192, sBh = sb + 16384, sBl = sb + 24576;

#pragma unroll
        for (int ks = 0; ks < 2; ks++) {
            uint32_t ah[4][4], bh[4][2], bl[4][2];
#pragma unroll
            for (int mt = 0; mt < 4; mt++) LDSM_X4(ah[mt], sAh + aoff[mt][ks]);
#pragma unroll
            for (int g = 0; g < 2; g++) {
                uint32_t r4[4];
                LDSM_X4(r4, sBh + boff[g][ks]);
                bh[2 * g][0] = r4[0]; bh[2 * g][1] = r4[1];
                bh[2 * g + 1][0] = r4[2]; bh[2 * g + 1][1] = r4[3];
                LDSM_X4(r4, sBl + boff[g][ks]);
                bl[2 * g][0] = r4[0]; bl[2 * g][1] = r4[1];
                bl[2 * g + 1][0] = r4[2]; bl[2 * g + 1][1] = r4[3];
            }
#pragma unroll
            for (int mt = 0; mt < 4; mt++)
#pragma unroll
                for (int nt = 0; nt < 4; nt++) {
                    MMA_BF16(acc[mt][nt], ah[mt], bh[nt]);
                    MMA_BF16(acc[mt][nt], ah[mt], bl[nt]);
                }
            uint32_t al[4][4];
#pragma unroll
            for (int mt = 0; mt < 4; mt++) LDSM_X4(al[mt], sAl + aoff[mt][ks]);
#pragma unroll
            for (int mt = 0; mt < 4; mt++)
#pragma unroll
                for (int nt = 0; nt < 4; nt++)
                    MMA_BF16(acc[mt][nt], al[mt], bh[nt]);
        }
        __syncthreads();
    }

    // ---- epilogue ----
#pragma unroll
    for (int mt = 0; mt < 4; mt++) {
#pragma unroll
        for (int nt = 0; nt < 4; nt++) {
#pragma unroll
            for (int half = 0; half < 2; half++) {
                int r  = row0 + wm0 + mt * 16 + (lane >> 2) + half * 8;
                int cg = col0 + wn0 + nt * 8 + (lane & 3) * 2;
                float v0 = acc[mt][nt][2 * half + 0];
                float v1 = acc[mt][nt][2 * half + 1];
                if (MODE == 0) {
                    int b = r >> 12, nrow = r & (NN - 1);
                    int region = cg >> 10;
                    int cc = cg & 1023;
                    int h = cc >> 6, d = cc & 63;
                    float* base = (region == 0) ? g_q : (region == 1) ? g_k : g_v;
                    if (region == 0) {
                        v0 = (v0 + bq[cc]) * 0.125f;
                        v1 = (v1 + bq[cc + 1]) * 0.125f;
                    }
                    *(float2*)(base + (((size_t)(b * HH + h) * NN) + nrow) * DHH + d) =
                        make_float2(v0, v1);
                } else {
                    *(float2*)(outp + (size_t)r * DIMM + cg) = make_float2(v0, v1);
                }
            }
        }
    }
}

// ---------------------------------------------------------------------------
// Windowed attention (fp32, online softmax). Bias staged in 32-key chunks so
// smem = 82 KB -> 2 CTAs/SM. grid (NBLK, H, B), 128 threads, 1 query/thread.
// Output written as bf16 hi/lo split (feeds HMMA GEMM2).
// ---------------------------------------------------------------------------
#define CHNK 32
#define SMEM_ATTN_BYTES ((8192 + 8192 + 128 * (CHNK + 1)) * 4)   // 82432

__device__ __forceinline__ void key_step(
    const float* __restrict__ sK, const float* __restrict__ sV,
    int j, float bj,
    const float (&q)[64], float (&acc)[64], float& m, float& l)
{
    const float4* k4 = reinterpret_cast<const float4*>(sK + j * 64);
    float s0 = 0.f, s1 = 0.f, s2 = 0.f, s3 = 0.f;
#pragma unroll
    for (int t = 0; t < 16; t++) {
        float4 kk = k4[t];
        s0 = fmaf(q[4 * t + 0], kk.x, s0);
        s1 = fmaf(q[4 * t + 1], kk.y, s1);
        s2 = fmaf(q[4 * t + 2], kk.z, s2);
        s3 = fmaf(q[4 * t + 3], kk.w, s3);
    }
    float s = (s0 + s1) + (s2 + s3) + bj;
    const float4* v4 = reinterpret_cast<const float4*>(sV + j * 64);

    if (s > m) {
        float sc = __expf(m - s);
        m = s;
        l = fmaf(l, sc, 1.f);
#pragma unroll
        for (int t = 0; t < 16; t++) {
            float4 vv = v4[t];
            acc[4 * t + 0] = fmaf(acc[4 * t + 0], sc, vv.x);
            acc[4 * t + 1] = fmaf(acc[4 * t + 1], sc, vv.y);
            acc[4 * t + 2] = fmaf(acc[4 * t + 2], sc, vv.z);
            acc[4 * t + 3] = fmaf(acc[4 * t + 3], sc, vv.w);
        }
    } else {
        float p = __expf(s - m);
        l += p;
#pragma unroll
        for (int t = 0; t < 16; t++) {
            float4 vv = v4[t];
            acc[4 * t + 0] = fmaf(p, vv.x, acc[4 * t + 0]);
            acc[4 * t + 1] = fmaf(p, vv.y, acc[4 * t + 1]);
            acc[4 * t + 2] = fmaf(p, vv.z, acc[4 * t + 2]);
            acc[4 * t + 3] = fmaf(p, vv.w, acc[4 * t + 3]);
        }
    }
}

__global__ __launch_bounds__(128, 2) void attn_kernel(
    const float* __restrict__ attn_bias,
    const float* __restrict__ memkv)
{
    extern __shared__ float smf[];
    float* sK = smf;                 // [128][64]
    float* sV = smf + 8192;          // [128][64]
    float* sB = smf + 16384;         // [128][CHNK+1]

    const int w   = blockIdx.x;
    const int h   = blockIdx.y;
    const int b   = blockIdx.z;
    const int tid = threadIdx.x;

    const size_t headbase = ((size_t)(b * HH + h) * NN) * DHH;
    const float* qp = g_q + headbase + (size_t)w * WW * DHH;

    // stage Q at stride-65 (uses sK/sV space), then read to regs
    for (int idx = tid; idx < WW * DHH; idx += 128) {
        int r = idx >> 6, c = idx & 63;
        smf[r * 65 + c] = qp[idx];
    }
    __syncthreads();
    float q[64];
#pragma unroll
    for (int d = 0; d < 64; d++) q[d] = smf[tid * 65 + d];
    __syncthreads();

    float m = -3.402823466e+38f, l = 0.f;
    float acc[64];
#pragma unroll
    for (int d = 0; d < 64; d++) acc[d] = 0.f;

    // ---- segment 0: memory KV (4 keys, bias 0) ----
    {
        const float* kp = memkv + (size_t)h * MMEM * DHH;
        const float* vp = memkv + (size_t)(HH + h) * MMEM * DHH;
        for (int idx = tid; idx < MMEM * DHH; idx += 128) {
            sK[idx] = kp[idx];
            sV[idx] = vp[idx];
        }
        __syncthreads();
        for (int j = 0; j < MMEM; j++)
            key_step(sK, sV, j, 0.f, q, acc, m, l);
    }

    // ---- segments 1 (prev window, skipped at w==0) and 2 (current) ----
    for (int seg = (w > 0 ? 0 : 1); seg < 2; seg++) {
        const int wk = w - 1 + seg;
        __syncthreads();                        // prior compute done
        const float* kp = g_k + headbase + (size_t)wk * WW * DHH;
        const float* vp = g_v + headbase + (size_t)wk * WW * DHH;
        for (int idx = tid; idx < WW * DHH; idx += 128) {
            sK[idx] = kp[idx];
            sV[idx] = vp[idx];
        }
        const float* bp = attn_bias + ((size_t)b * NN + (size_t)w * WW) * NN
                        + (size_t)wk * WW;
        for (int ch = 0; ch < WW / CHNK; ch++) {
            if (ch) __syncthreads();            // sB reuse guard
            const float* bpc = bp + ch * CHNK;
            for (int idx = tid; idx < 128 * CHNK; idx += 128) {
                int rr = idx >> 5, cc2 = idx & (CHNK - 1);
                sB[rr * (CHNK + 1) + cc2] = bpc[(size_t)rr * NN + cc2];
            }
            __syncthreads();                    // covers KV (ch==0) + sB
#pragma unroll 1
            for (int j = 0; j < CHNK; j++)
                key_step(sK, sV, ch * CHNK + j, sB[tid * (CHNK + 1) + j], q, acc, m, l);
        }
    }

    // ---- finalize: bf16 hi/lo split, token-major [b][n][h*64+d] ----
    float inv = 1.f / l;
    size_t obase = ((size_t)b * NN + (size_t)w * WW + tid) * DI + h * DHH;
    uint2* oh = (uint2*)(g_oh + obase);
    uint2* ol = (uint2*)(g_ol + obase);
#pragma unroll
    for (int t = 0; t < 16; t++) {
        float v0 = acc[4 * t + 0] * inv, v1 = acc[4 * t + 1] * inv;
        float v2 = acc[4 * t + 2] * inv, v3 = acc[4 * t + 3] * inv;
        uint2 hv, lv;
        split2(v0, v1, hv.x, lv.x);
        split2(v2, v3, hv.y, lv.y);
        oh[t] = hv;
        ol[t] = lv;
    }
}

// ---------------------------------------------------------------------------
// Launch. inputs: 0 x, 1 mask (all-True), 2 attn_bias, 3 Wq, 4 bq, 5 Wkv,
//                 6 Wo, 7 memory_kv
// ---------------------------------------------------------------------------
extern "C" void kernel_launch(void* const* d_in, const int* in_sizes, int n_in,
                              void* d_out, int out_size)
{
    const float* x    = (const float*)d_in[0];
    const float* bias = (const float*)d_in[2];
    const float* Wq   = (const float*)d_in[3];
    const float* bq   = (const float*)d_in[4];
    const float* Wkv  = (const float*)d_in[5];
    const float* Wo   = (const float*)d_in[6];
    const float* mkv  = (const float*)d_in[7];
    float* out = (float*)d_out;

    cudaFuncSetAttribute(gemm_mma_kernel<DIMM, 0>,
                         cudaFuncAttributeMaxDynamicSharedMemorySize, GEMM_SMEM);
    cudaFuncSetAttribute(gemm_mma_kernel<DI, 1>,
                         cudaFuncAttributeMaxDynamicSharedMemorySize, GEMM_SMEM);
    cudaFuncSetAttribute(attn_kernel,
                         cudaFuncAttributeMaxDynamicSharedMemorySize, SMEM_ATTN_BYTES);

    // 0) prep: weight transpose+split, x split
    {
        dim3 blk(32, 8);
        transpose_split_kernel<0><<<dim3(1024 / 32, 768 / 32), blk>>>(Wq);
        transpose_split_kernel<1><<<dim3(2048 / 32, 768 / 32), blk>>>(Wkv);
        transpose_split_kernel<2><<<dim3(768 / 32, 1024 / 32), blk>>>(Wo);
        split_x_kernel<<<2048, 256>>>(x);
    }

    // 1) QKV projection (HMMA): [8192,768] x [768,3072] -> g_q/g_k/g_v
    {
        __nv_bfloat16 *xh, *xl, *wh, *wl;
        cudaGetSymbolAddress((void**)&xh, g_xh);
        cudaGetSymbolAddress((void**)&xl, g_xl);
        cudaGetSymbolAddress((void**)&wh, g_wt_h);
        cudaGetSymbolAddress((void**)&wl, g_wt_l);
        gemm_mma_kernel<DIMM, 0><<<dim3(3 * DI / 128, BB * NN / 128), 256, GEMM_SMEM>>>(
            xh, xl, wh, wl, bq, nullptr);
    }

    // 2) windowed attention -> g_oh/g_ol
    attn_kernel<<<dim3(NBLK, HH, BB), 128, SMEM_ATTN_BYTES>>>(bias, mkv);

    // 3) output projection (HMMA): [8192,1024] x [1024,768] -> out
    {
        __nv_bfloat16 *oh, *ol, *wh, *wl;
        cudaGetSymbolAddress((void**)&oh, g_oh);
        cudaGetSymbolAddress((void**)&ol, g_ol);
        cudaGetSymbolAddress((void**)&wh, g_wot_h);
        cudaGetSymbolAddress((void**)&wl, g_wot_l);
        gemm_mma_kernel<DI, 1><<<dim3(DIMM / 128, BB * NN / 128), 256, GEMM_SMEM>>>(
            oh, ol, wh, wl, nullptr, out);
    }
}

// round 6
// speedup vs baseline: 3.5389x; 1.7409x over previous
#include <cuda_runtime.h>
#include <cuda_bf16.h>
#include <cstdint>
#include <cstddef>

// Problem constants
#define BB    2
#define NN    4096
#define DIMM  768
#define HH    16
#define DHH   64
#define DI    1024          // H*DH
#define WW    128
#define MMEM  4
#define NBLK  32            // NN / WW
#define NEGF  (-3.4028235e+38f)

// ---------------------------------------------------------------------------
// Scratch (device globals; no allocation allowed)
// ---------------------------------------------------------------------------
#define QKV_ELEMS ((size_t)BB * HH * NN * DHH)
__device__ __align__(16) __nv_bfloat16 g_qh[QKV_ELEMS];
__device__ __align__(16) __nv_bfloat16 g_ql[QKV_ELEMS];
__device__ __align__(16) __nv_bfloat16 g_kh[QKV_ELEMS];
__device__ __align__(16) __nv_bfloat16 g_kl[QKV_ELEMS];
__device__ __align__(16) __nv_bfloat16 g_vh[QKV_ELEMS];
__device__ __align__(16) __nv_bfloat16 g_vl[QKV_ELEMS];

// bf16 hi/lo splits of x and attention output
__device__ __align__(16) __nv_bfloat16 g_xh[(size_t)BB * NN * DIMM];
__device__ __align__(16) __nv_bfloat16 g_xl[(size_t)BB * NN * DIMM];
__device__ __align__(16) __nv_bfloat16 g_oh[(size_t)BB * NN * DI];
__device__ __align__(16) __nv_bfloat16 g_ol[(size_t)BB * NN * DI];

// transposed, bf16-split weights
__device__ __align__(16) __nv_bfloat16 g_wt_h[(size_t)3072 * 768];
__device__ __align__(16) __nv_bfloat16 g_wt_l[(size_t)3072 * 768];
__device__ __align__(16) __nv_bfloat16 g_wot_h[(size_t)768 * 1024];
__device__ __align__(16) __nv_bfloat16 g_wot_l[(size_t)768 * 1024];

// padded memory-KV: [2(kv)][H][16 rows][64] bf16 hi/lo (rows 4..15 zero)
__device__ __align__(16) __nv_bfloat16 g_memh[2 * HH * 16 * 64];
__device__ __align__(16) __nv_bfloat16 g_meml[2 * HH * 16 * 64];

// ---------------------------------------------------------------------------
// PTX helpers (baseline ISA: mma.sync / ldmatrix / cp.async)
// ---------------------------------------------------------------------------
__device__ __forceinline__ uint32_t smem_u32(const void* p) {
    uint32_t a;
    asm("{ .reg .u64 t; cvta.to.shared.u64 t, %1; cvt.u32.u64 %0, t; }"
        : "=r"(a) : "l"(p));
    return a;
}

#define CP_ASYNC16(dst, src) \
    asm volatile("cp.async.cg.shared.global [%0], [%1], 16;" :: "r"(dst), "l"(src))
#define CP_COMMIT() asm volatile("cp.async.commit_group;" ::: "memory")
#define CP_WAIT(n)  asm volatile("cp.async.wait_group %0;" :: "n"(n) : "memory")

#define LDSM_X4(r, addr) \
    asm volatile("ldmatrix.sync.aligned.m8n8.x4.shared.b16 {%0,%1,%2,%3}, [%4];" \
        : "=r"((r)[0]), "=r"((r)[1]), "=r"((r)[2]), "=r"((r)[3]) : "r"(addr))

#define LDSM_X4_T(r, addr) \
    asm volatile("ldmatrix.sync.aligned.m8n8.x4.trans.shared.b16 {%0,%1,%2,%3}, [%4];" \
        : "=r"((r)[0]), "=r"((r)[1]), "=r"((r)[2]), "=r"((r)[3]) : "r"(addr))

#define MMA_BF16(c, a, b) \
    asm volatile("mma.sync.aligned.m16n8k16.row.col.f32.bf16.bf16.f32 " \
        "{%0,%1,%2,%3}, {%4,%5,%6,%7}, {%8,%9}, {%0,%1,%2,%3};" \
        : "+f"((c)[0]), "+f"((c)[1]), "+f"((c)[2]), "+f"((c)[3]) \
        : "r"((a)[0]), "r"((a)[1]), "r"((a)[2]), "r"((a)[3]), \
          "r"((b)[0]), "r"((b)[1]))

#define MMA2(c, a, b0v, b1v) \
    asm volatile("mma.sync.aligned.m16n8k16.row.col.f32.bf16.bf16.f32 " \
        "{%0,%1,%2,%3}, {%4,%5,%6,%7}, {%8,%9}, {%0,%1,%2,%3};" \
        : "+f"((c)[0]), "+f"((c)[1]), "+f"((c)[2]), "+f"((c)[3]) \
        : "r"((a)[0]), "r"((a)[1]), "r"((a)[2]), "r"((a)[3]), \
          "r"(b0v), "r"(b1v))

// swizzles
__device__ __forceinline__ uint32_t swz64(uint32_t off) {      // 64-B rows
    return off ^ ((off >> 3) & 0x30);
}
__device__ __forceinline__ uint32_t swz128(uint32_t off) {     // 128-B rows
    return off ^ ((off >> 3) & 0x70);
}

// ---------------------------------------------------------------------------
// bf16 split helper
// ---------------------------------------------------------------------------
__device__ __forceinline__ void split2(float f0, float f1, uint32_t& hw, uint32_t& lw) {
    __nv_bfloat16 h0 = __float2bfloat16_rn(f0);
    __nv_bfloat16 h1 = __float2bfloat16_rn(f1);
    __nv_bfloat16 l0 = __float2bfloat16_rn(f0 - __bfloat162float(h0));
    __nv_bfloat16 l1 = __float2bfloat16_rn(f1 - __bfloat162float(h1));
    hw = (uint32_t)__bfloat16_as_ushort(h0) | ((uint32_t)__bfloat16_as_ushort(h1) << 16);
    lw = (uint32_t)__bfloat16_as_ushort(l0) | ((uint32_t)__bfloat16_as_ushort(l1) << 16);
}

// ---------------------------------------------------------------------------
// Prep 1: transpose + bf16-split weights
// ---------------------------------------------------------------------------
template <int W>
__global__ void transpose_split_kernel(const float* __restrict__ src)
{
    constexpr int R = (W == 2) ? 1024 : 768;
    constexpr int C = (W == 0) ? 1024 : (W == 1) ? 2048 : 768;
    __nv_bfloat16* dh = (W == 0) ? g_wt_h : (W == 1) ? (g_wt_h + (size_t)1024 * 768) : g_wot_h;
    __nv_bfloat16* dl = (W == 0) ? g_wt_l : (W == 1) ? (g_wt_l + (size_t)1024 * 768) : g_wot_l;

    __shared__ float tile[32][33];
    int c0 = blockIdx.x * 32, r0 = blockIdx.y * 32;
    int tx = threadIdx.x, ty = threadIdx.y;
#pragma unroll
    for (int i = 0; i < 32; i += 8)
        tile[ty + i][tx] = src[(size_t)(r0 + ty + i) * C + c0 + tx];
    __syncthreads();
#pragma unroll
    for (int i = 0; i < 32; i += 8) {
        float f = tile[tx][ty + i];
        __nv_bfloat16 h = __float2bfloat16_rn(f);
        __nv_bfloat16 l = __float2bfloat16_rn(f - __bfloat162float(h));
        size_t o = (size_t)(c0 + ty + i) * R + (r0 + tx);
        dh[o] = h;
        dl[o] = l;
    }
}

// ---------------------------------------------------------------------------
// Prep 2: elementwise split of x
// ---------------------------------------------------------------------------
__global__ void split_x_kernel(const float* __restrict__ x)
{
    const int N4 = (BB * NN * DIMM) / 4;
    for (int i = blockIdx.x * blockDim.x + threadIdx.x; i < N4;
         i += gridDim.x * blockDim.x) {
        float4 f = ((const float4*)x)[i];
        uint2 hv, lv;
        split2(f.x, f.y, hv.x, lv.x);
        split2(f.z, f.w, hv.y, lv.y);
        ((uint2*)g_xh)[i] = hv;
        ((uint2*)g_xl)[i] = lv;
    }
}

// ---------------------------------------------------------------------------
// Prep 3: memory_kv [2][H][4][64] fp32 -> padded bf16 hi/lo [2][H][16][64]
// ---------------------------------------------------------------------------
__global__ void memprep_kernel(const float* __restrict__ mkv)
{
    int idx = blockIdx.x * 256 + threadIdx.x;        // 0..32767
    if (idx >= 2 * HH * 16 * 64) return;
    int d = idx & 63;
    int r = (idx >> 6) & 15;
    int rest = idx >> 10;                            // kv*HH + h
    float f = (r < MMEM) ? mkv[(size_t)(rest * MMEM + r) * 64 + d] : 0.f;
    __nv_bfloat16 hi = __float2bfloat16_rn(f);
    __nv_bfloat16 lo = __float2bfloat16_rn(f - __bfloat162float(hi));
    g_memh[idx] = hi;
    g_meml[idx] = lo;
}

// ---------------------------------------------------------------------------
// HMMA GEMM (as R5): 128x128 tile, BK=32, 2-stage cp.async, SW64 smem.
//   MODE 0: epilogue scatters q/k/v as bf16 hi/lo head-major (q: +bias, *0.125)
//   MODE 1: plain fp32 out
// ---------------------------------------------------------------------------
#define GEMM_SMEM 65536

template <int K, int MODE>
__global__ __launch_bounds__(256, 2)
void gemm_mma_kernel(const __nv_bfloat16* __restrict__ Ah,
                     const __nv_bfloat16* __restrict__ Al,
                     const __nv_bfloat16* __restrict__ Bh,
                     const __nv_bfloat16* __restrict__ Bl,
                     const float* __restrict__ bq,
                     float* __restrict__ outp)
{
    extern __shared__ __align__(1024) char sm[];
    const uint32_t smb = smem_u32(sm);

    constexpr int NC = K / 32;
    const int row0 = blockIdx.y * 128;
    const int col0 = blockIdx.x * 128;
    const int t    = threadIdx.x;
    const int lane = t & 31;
    const int wid  = t >> 5;
    const int wm0  = (wid >> 2) * 64;
    const int wn0  = (wid & 3) * 32;

    uint32_t ldst[2];
    const __nv_bfloat16 *pAh[2], *pAl[2], *pBh[2], *pBl[2];
#pragma unroll
    for (int r = 0; r < 2; r++) {
        int idx = t + 256 * r;
        int row = idx >> 2, c4 = idx & 3;
        ldst[r] = swz64((uint32_t)(row * 64 + c4 * 16));
        pAh[r] = Ah + (size_t)(row0 + row) * K + c4 * 8;
        pAl[r] = Al + (size_t)(row0 + row) * K + c4 * 8;
        pBh[r] = Bh + (size_t)(col0 + row) * K + c4 * 8;
        pBl[r] = Bl + (size_t)(col0 + row) * K + c4 * 8;
    }

    uint32_t aoff[4][2];
    {
        int arow = (lane & 7) + (lane & 8);
        int akb  = ((lane >> 4) & 1) * 16;
#pragma unroll
        for (int mt = 0; mt < 4; mt++)
#pragma unroll
            for (int ks = 0; ks < 2; ks++)
                aoff[mt][ks] = swz64((uint32_t)((wm0 + mt * 16 + arow) * 64 + ks * 32 + akb));
    }
    uint32_t boff[2][2];
    {
        int brow = ((lane >> 4) & 1) * 8 + (lane & 7);
        int bkb  = ((lane >> 3) & 1) * 16;
#pragma unroll
        for (int g = 0; g < 2; g++)
#pragma unroll
            for (int ks = 0; ks < 2; ks++)
                boff[g][ks] = swz64((uint32_t)((wn0 + g * 16 + brow) * 64 + ks * 32 + bkb));
    }

    float acc[4][4][4];
#pragma unroll
    for (int i = 0; i < 4; i++)
#pragma unroll
        for (int j = 0; j < 4; j++)
#pragma unroll
            for (int r = 0; r < 4; r++) acc[i][j][r] = 0.f;

#pragma unroll
    for (int r = 0; r < 2; r++) {
        CP_ASYNC16(smb + ldst[r],          (const char*)pAh[r]);
        CP_ASYNC16(smb + 8192  + ldst[r],  (const char*)pAl[r]);
        CP_ASYNC16(smb + 16384 + ldst[r],  (const char*)pBh[r]);
        CP_ASYNC16(smb + 24576 + ldst[r],  (const char*)pBl[r]);
    }
    CP_COMMIT();

    for (int c = 0; c < NC; c++) {
        if (c + 1 < NC) {
            uint32_t sb = smb + ((c + 1) & 1) * 32768;
            int koff = (c + 1) * 32;
#pragma unroll
            for (int r = 0; r < 2; r++) {
                CP_ASYNC16(sb + ldst[r],         (const char*)(pAh[r] + koff));
                CP_ASYNC16(sb + 8192  + ldst[r], (const char*)(pAl[r] + koff));
                CP_ASYNC16(sb + 16384 + ldst[r], (const char*)(pBh[r] + koff));
                CP_ASYNC16(sb + 24576 + ldst[r], (const char*)(pBl[r] + koff));
            }
            CP_COMMIT();
            CP_WAIT(1);
        } else {
            CP_WAIT(0);
        }
        __syncthreads();

        const uint32_t sb  = smb + (c & 1) * 32768;
        const uint32_t sAh = sb, sAl = sb + 8192, sBh = sb + 16384, sBl = sb + 24576;

#pragma unroll
        for (int ks = 0; ks < 2; ks++) {
            uint32_t ah[4][4], bh[4][2], bl[4][2];
#pragma unroll
            for (int mt = 0; mt < 4; mt++) LDSM_X4(ah[mt], sAh + aoff[mt][ks]);
#pragma unroll
            for (int g = 0; g < 2; g++) {
                uint32_t r4[4];
                LDSM_X4(r4, sBh + boff[g][ks]);
                bh[2 * g][0] = r4[0]; bh[2 * g][1] = r4[1];
                bh[2 * g + 1][0] = r4[2]; bh[2 * g + 1][1] = r4[3];
                LDSM_X4(r4, sBl + boff[g][ks]);
                bl[2 * g][0] = r4[0]; bl[2 * g][1] = r4[1];
                bl[2 * g + 1][0] = r4[2]; bl[2 * g + 1][1] = r4[3];
            }
#pragma unroll
            for (int mt = 0; mt < 4; mt++)
#pragma unroll
                for (int nt = 0; nt < 4; nt++) {
                    MMA_BF16(acc[mt][nt], ah[mt], bh[nt]);
                    MMA_BF16(acc[mt][nt], ah[mt], bl[nt]);
                }
            uint32_t al[4][4];
#pragma unroll
            for (int mt = 0; mt < 4; mt++) LDSM_X4(al[mt], sAl + aoff[mt][ks]);
#pragma unroll
            for (int mt = 0; mt < 4; mt++)
#pragma unroll
                for (int nt = 0; nt < 4; nt++)
                    MMA_BF16(acc[mt][nt], al[mt], bh[nt]);
        }
        __syncthreads();
    }

    // ---- epilogue ----
#pragma unroll
    for (int mt = 0; mt < 4; mt++) {
#pragma unroll
        for (int nt = 0; nt < 4; nt++) {
#pragma unroll
            for (int half = 0; half < 2; half++) {
                int r  = row0 + wm0 + mt * 16 + (lane >> 2) + half * 8;
                int cg = col0 + wn0 + nt * 8 + (lane & 3) * 2;
                float v0 = acc[mt][nt][2 * half + 0];
                float v1 = acc[mt][nt][2 * half + 1];
                if (MODE == 0) {
                    int b = r >> 12, nrow = r & (NN - 1);
                    int region = cg >> 10;
                    int cc = cg & 1023;
                    int h = cc >> 6, d = cc & 63;
                    if (region == 0) {
                        v0 = (v0 + bq[cc]) * 0.125f;
                        v1 = (v1 + bq[cc + 1]) * 0.125f;
                    }
                    __nv_bfloat16* dh = (region == 0) ? g_qh : (region == 1) ? g_kh : g_vh;
                    __nv_bfloat16* dl = (region == 0) ? g_ql : (region == 1) ? g_kl : g_vl;
                    size_t off = (((size_t)(b * HH + h) * NN) + nrow) * DHH + d;
                    uint32_t hv, lv;
                    split2(v0, v1, hv, lv);
                    *(uint32_t*)(dh + off) = hv;
                    *(uint32_t*)(dl + off) = lv;
                } else {
                    *(float2*)(outp + (size_t)r * DIMM + cg) = make_float2(v0, v1);
                }
            }
        }
    }
}

// ---------------------------------------------------------------------------
// HMMA windowed attention.
//   grid (H, NBLK, B) [h fastest -> bias L2 reuse x16], 256 thr = 8 warps,
//   each warp owns 16 query rows. Keys processed in chunks: mem(16 padded),
//   then 64-key chunks of prev/cur windows, online softmax in frag layout.
// smem: buf0[0,32768) buf1[32768,65536) (each: Kh|Kl|Vh|Vl 8KB ea, 64 rows),
//       mem buffer [65536,73728) (16-row chunk), Q staged in buf0 initially.
// ---------------------------------------------------------------------------
#define ATTN_SMEM 73728

template <int NK, bool HASBIAS>
__device__ __forceinline__ void attn_chunk(
    uint32_t bufb, const float* bptr,
    const uint32_t (&qh)[4][4], const uint32_t (&ql)[4][4],
    float (&o)[8][4], float& m0, float& m1, float& l0, float& l1, int lane)
{
    constexpr int NT = NK / 8;
    constexpr int NG = NK / 16;
    constexpr uint32_t KL = (uint32_t)NK * 128u;
    constexpr uint32_t VH = 2u * NK * 128u;
    constexpr uint32_t VL = 3u * NK * 128u;

    // bias prefetch (rows r, r+8; cols nt*8 + 2q)
    float2 bv[2][8];
    if (HASBIAS) {
#pragma unroll
        for (int hr = 0; hr < 2; hr++)
#pragma unroll
            for (int nt = 0; nt < NT; nt++)
                bv[hr][nt] = *(const float2*)(bptr + (size_t)hr * 8 * NN + nt * 8);
    }

    float s[NT][4];
#pragma unroll
    for (int nt = 0; nt < NT; nt++)
        s[nt][0] = s[nt][1] = s[nt][2] = s[nt][3] = 0.f;

    // ---- S = Q K^T (3-pass split) ----
    const int brow = ((lane >> 4) & 1) * 8 + (lane & 7);
    const int bkb  = ((lane >> 3) & 1) * 16;
#pragma unroll
    for (int kc = 0; kc < 4; kc++) {
#pragma unroll
        for (int ng = 0; ng < NG; ng++) {
            uint32_t bo = swz128((uint32_t)((ng * 16 + brow) * 128 + kc * 32 + bkb));
            uint32_t bh4[4], bl4[4];
            LDSM_X4(bh4, bufb + bo);
            LDSM_X4(bl4, bufb + KL + bo);
            MMA2(s[2 * ng],     qh[kc], bh4[0], bh4[1]);
            MMA2(s[2 * ng + 1], qh[kc], bh4[2], bh4[3]);
            MMA2(s[2 * ng],     qh[kc], bl4[0], bl4[1]);
            MMA2(s[2 * ng + 1], qh[kc], bl4[2], bl4[3]);
            MMA2(s[2 * ng],     ql[kc], bh4[0], bh4[1]);
            MMA2(s[2 * ng + 1], ql[kc], bh4[2], bh4[3]);
        }
    }

    if (!HASBIAS) {
        // mem chunk: only cols 0..3 valid
        if ((lane & 3) >= 2) { s[0][0] = s[0][1] = s[0][2] = s[0][3] = NEGF; }
        s[1][0] = s[1][1] = s[1][2] = s[1][3] = NEGF;
    } else {
#pragma unroll
        for (int nt = 0; nt < NT; nt++) {
            s[nt][0] += bv[0][nt].x;
            s[nt][1] += bv[0][nt].y;
            s[nt][2] += bv[1][nt].x;
            s[nt][3] += bv[1][nt].y;
        }
    }

    // ---- online softmax (rows r = lane>>2 and r+8) ----
    float mx0 = NEGF, mx1 = NEGF;
#pragma unroll
    for (int nt = 0; nt < NT; nt++) {
        mx0 = fmaxf(mx0, fmaxf(s[nt][0], s[nt][1]));
        mx1 = fmaxf(mx1, fmaxf(s[nt][2], s[nt][3]));
    }
    mx0 = fmaxf(mx0, __shfl_xor_sync(0xffffffffu, mx0, 1));
    mx0 = fmaxf(mx0, __shfl_xor_sync(0xffffffffu, mx0, 2));
    mx1 = fmaxf(mx1, __shfl_xor_sync(0xffffffffu, mx1, 1));
    mx1 = fmaxf(mx1, __shfl_xor_sync(0xffffffffu, mx1, 2));
    float mn0 = fmaxf(m0, mx0), mn1 = fmaxf(m1, mx1);
    float sc0 = __expf(m0 - mn0), sc1 = __expf(m1 - mn1);
    float sum0 = 0.f, sum1 = 0.f;
#pragma unroll
    for (int nt = 0; nt < NT; nt++) {
        s[nt][0] = __expf(s[nt][0] - mn0);
        s[nt][1] = __expf(s[nt][1] - mn0);
        s[nt][2] = __expf(s[nt][2] - mn1);
        s[nt][3] = __expf(s[nt][3] - mn1);
        sum0 += s[nt][0] + s[nt][1];
        sum1 += s[nt][2] + s[nt][3];
    }
    sum0 += __shfl_xor_sync(0xffffffffu, sum0, 1);
    sum0 += __shfl_xor_sync(0xffffffffu, sum0, 2);
    sum1 += __shfl_xor_sync(0xffffffffu, sum1, 1);
    sum1 += __shfl_xor_sync(0xffffffffu, sum1, 2);
    l0 = l0 * sc0 + sum0;
    l1 = l1 * sc1 + sum1;
    m0 = mn0;
    m1 = mn1;
#pragma unroll
    for (int d = 0; d < 8; d++) {
        o[d][0] *= sc0; o[d][1] *= sc0;
        o[d][2] *= sc1; o[d][3] *= sc1;
    }

    // ---- P fragments (bf16 hi/lo, A-operand layout) ----
    uint32_t ph[NG][4], pl[NG][4];
#pragma unroll
    for (int kc = 0; kc < NG; kc++) {
        split2(s[2 * kc][0],     s[2 * kc][1],     ph[kc][0], pl[kc][0]);
        split2(s[2 * kc][2],     s[2 * kc][3],     ph[kc][1], pl[kc][1]);
        split2(s[2 * kc + 1][0], s[2 * kc + 1][1], ph[kc][2], pl[kc][2]);
        split2(s[2 * kc + 1][2], s[2 * kc + 1][3], ph[kc][3], pl[kc][3]);
    }

    // ---- O += P V (3-pass split), V via ldmatrix.trans ----
    const int vrow = (lane & 7) + 8 * ((lane >> 3) & 1);
    const int vdb  = 16 * ((lane >> 4) & 1);
#pragma unroll
    for (int dg = 0; dg < 4; dg++) {
#pragma unroll
        for (int kc = 0; kc < NG; kc++) {
            uint32_t vo = swz128((uint32_t)((kc * 16 + vrow) * 128 + dg * 32 + vdb));
            uint32_t vh4[4], vl4[4];
            LDSM_X4_T(vh4, bufb + VH + vo);
            LDSM_X4_T(vl4, bufb + VL + vo);
            MMA2(o[2 * dg],     ph[kc], vh4[0], vh4[1]);
            MMA2(o[2 * dg + 1], ph[kc], vh4[2], vh4[3]);
            MMA2(o[2 * dg],     ph[kc], vl4[0], vl4[1]);
            MMA2(o[2 * dg + 1], ph[kc], vl4[2], vl4[3]);
            MMA2(o[2 * dg],     pl[kc], vh4[0], vh4[1]);
            MMA2(o[2 * dg + 1], pl[kc], vh4[2], vh4[3]);
        }
    }
}

__device__ __forceinline__ void attn_load_chunk(uint32_t smb, int t, int c, int w,
                                                size_t headoff)
{
    uint32_t bb = smb + ((c & 1) ? 0u : 32768u);
    int wk = (w > 0) ? (w - 1 + (c >> 1)) : 0;
    size_t rowg = headoff + ((size_t)wk * WW + (size_t)(c & 1) * 64) * DHH;
    const char* kh = (const char*)(g_kh + rowg);
    const char* kl = (const char*)(g_kl + rowg);
    const char* vh = (const char*)(g_vh + rowg);
    const char* vl = (const char*)(g_vl + rowg);
#pragma unroll
    for (int rr = 0; rr < 2; rr++) {
        uint32_t bo = (uint32_t)(t + 256 * rr) * 16;   // row*128 + c16*16
        uint32_t sw = swz128(bo);
        CP_ASYNC16(bb + sw,         kh + bo);
        CP_ASYNC16(bb + 8192 + sw,  kl + bo);
        CP_ASYNC16(bb + 16384 + sw, vh + bo);
        CP_ASYNC16(bb + 24576 + sw, vl + bo);
    }
    CP_COMMIT();
}

__global__ __launch_bounds__(256)
void attn_mma_kernel(const float* __restrict__ bias)
{
    extern __shared__ __align__(1024) char sm[];
    const uint32_t smb = smem_u32(sm);
    const int h = blockIdx.x, w = blockIdx.y, b = blockIdx.z;
    const int t = threadIdx.x, lane = t & 31, wid = t >> 5;
    const int wm0 = wid * 16;

    const size_t headoff = ((size_t)(b * HH + h) * NN) * DHH;

    // G1: stage Q (hi at 0, lo at 16384)
    {
        const char* qhp = (const char*)(g_qh + headoff + (size_t)w * WW * DHH);
        const char* qlp = (const char*)(g_ql + headoff + (size_t)w * WW * DHH);
#pragma unroll
        for (int rr = 0; rr < 4; rr++) {
            uint32_t bo = (uint32_t)(t + 256 * rr) * 16;
            uint32_t sw = swz128(bo);
            CP_ASYNC16(smb + sw,         qhp + bo);
            CP_ASYNC16(smb + 16384 + sw, qlp + bo);
        }
        CP_COMMIT();
    }
    // G2: mem KV (16 padded rows) at 65536
    {
        if (t < 128) {
            uint32_t bo = (uint32_t)t * 16;
            uint32_t sw = swz128(bo);
            const char* kh = (const char*)(g_memh + (size_t)(0 * HH + h) * 16 * 64);
            const char* kl = (const char*)(g_meml + (size_t)(0 * HH + h) * 16 * 64);
            const char* vh = (const char*)(g_memh + (size_t)(1 * HH + h) * 16 * 64);
            const char* vl = (const char*)(g_meml + (size_t)(1 * HH + h) * 16 * 64);
            CP_ASYNC16(smb + 65536 + sw,        kh + bo);
            CP_ASYNC16(smb + 65536 + 2048 + sw, kl + bo);
            CP_ASYNC16(smb + 65536 + 4096 + sw, vh + bo);
            CP_ASYNC16(smb + 65536 + 6144 + sw, vl + bo);
        }
        CP_COMMIT();
    }
    const int nch = (w > 0) ? 4 : 2;
    attn_load_chunk(smb, t, 0, w, headoff);          // G3 -> buf1
    CP_WAIT(2);
    __syncthreads();

    // Q fragments
    uint32_t qh[4][4], ql[4][4];
    {
        uint32_t arow = (uint32_t)(wm0 + (lane & 15));
        uint32_t akb  = ((lane >> 4) & 1) * 16;
#pragma unroll
        for (int kc = 0; kc < 4; kc++) {
            uint32_t off = swz128(arow * 128 + kc * 32 + akb);
            LDSM_X4(qh[kc], smb + off);
            LDSM_X4(ql[kc], smb + 16384 + off);
        }
    }
    __syncthreads();
    attn_load_chunk(smb, t, 1, w, headoff);          // G4 -> buf0
    CP_WAIT(2);                                      // mem (G2) done
    __syncthreads();

    float o[8][4];
#pragma unroll
    for (int i = 0; i < 8; i++)
        o[i][0] = o[i][1] = o[i][2] = o[i][3] = 0.f;
    float m0 = NEGF, m1 = NEGF, l0 = 0.f, l1 = 0.f;

    // mem segment
    attn_chunk<16, false>(smb + 65536, nullptr, qh, ql, o, m0, m1, l0, l1, lane);

    const int qr0 = w * WW + wm0 + (lane >> 2);
    for (int c = 0; c < nch; c++) {
        if (c + 1 < nch) CP_WAIT(1); else CP_WAIT(0);
        __syncthreads();
        int wk = (w > 0) ? (w - 1 + (c >> 1)) : 0;
        const float* bptr = bias + ((size_t)b * NN + qr0) * NN
                          + (size_t)wk * WW + (size_t)(c & 1) * 64 + 2 * (lane & 3);
        uint32_t bufb = smb + ((c & 1) ? 0u : 32768u);
        attn_chunk<64, true>(bufb, bptr, qh, ql, o, m0, m1, l0, l1, lane);
        __syncthreads();
        if (c + 2 < nch) attn_load_chunk(smb, t, c + 2, w, headoff);
    }

    // epilogue: write bf16 hi/lo token-major [b][n][h*64+d]
    float inv0 = 1.f / l0, inv1 = 1.f / l1;
    const int gr0 = qr0, gr1 = qr0 + 8;
#pragma unroll
    for (int nt = 0; nt < 8; nt++) {
        int d = h * 64 + nt * 8 + 2 * (lane & 3);
        size_t o0 = ((size_t)b * NN + gr0) * DI + d;
        size_t o1 = ((size_t)b * NN + gr1) * DI + d;
        uint32_t hv, lv;
        split2(o[nt][0] * inv0, o[nt][1] * inv0, hv, lv);
        *(uint32_t*)(g_oh + o0) = hv;
        *(uint32_t*)(g_ol + o0) = lv;
        split2(o[nt][2] * inv1, o[nt][3] * inv1, hv, lv);
        *(uint32_t*)(g_oh + o1) = hv;
        *(uint32_t*)(g_ol + o1) = lv;
    }
}

// ---------------------------------------------------------------------------
// Launch. inputs: 0 x, 1 mask (all-True), 2 attn_bias, 3 Wq, 4 bq, 5 Wkv,
//                 6 Wo, 7 memory_kv
// ---------------------------------------------------------------------------
extern "C" void kernel_launch(void* const* d_in, const int* in_sizes, int n_in,
                              void* d_out, int out_size)
{
    const float* x    = (const float*)d_in[0];
    const float* bias = (const float*)d_in[2];
    const float* Wq   = (const float*)d_in[3];
    const float* bq   = (const float*)d_in[4];
    const float* Wkv  = (const float*)d_in[5];
    const float* Wo   = (const float*)d_in[6];
    const float* mkv  = (const float*)d_in[7];
    float* out = (float*)d_out;

    cudaFuncSetAttribute(gemm_mma_kernel<DIMM, 0>,
                         cudaFuncAttributeMaxDynamicSharedMemorySize, GEMM_SMEM);
    cudaFuncSetAttribute(gemm_mma_kernel<DI, 1>,
                         cudaFuncAttributeMaxDynamicSharedMemorySize, GEMM_SMEM);
    cudaFuncSetAttribute(attn_mma_kernel,
                         cudaFuncAttributeMaxDynamicSharedMemorySize, ATTN_SMEM);

    // 0) prep
    {
        dim3 blk(32, 8);
        transpose_split_kernel<0><<<dim3(1024 / 32, 768 / 32), blk>>>(Wq);
        transpose_split_kernel<1><<<dim3(2048 / 32, 768 / 32), blk>>>(Wkv);
        transpose_split_kernel<2><<<dim3(768 / 32, 1024 / 32), blk>>>(Wo);
        split_x_kernel<<<2048, 256>>>(x);
        memprep_kernel<<<128, 256>>>(mkv);
    }

    // 1) QKV projection (HMMA) -> q/k/v bf16 hi/lo head-major
    {
        __nv_bfloat16 *xh, *xl, *wh, *wl;
        cudaGetSymbolAddress((void**)&xh, g_xh);
        cudaGetSymbolAddress((void**)&xl, g_xl);
        cudaGetSymbolAddress((void**)&wh, g_wt_h);
        cudaGetSymbolAddress((void**)&wl, g_wt_l);
        gemm_mma_kernel<DIMM, 0><<<dim3(3 * DI / 128, BB * NN / 128), 256, GEMM_SMEM>>>(
            xh, xl, wh, wl, bq, nullptr);
    }

    // 2) HMMA windowed attention -> g_oh/g_ol
    attn_mma_kernel<<<dim3(HH, NBLK, BB), 256, ATTN_SMEM>>>(bias);

    // 3) output projection (HMMA) -> out
    {
        __nv_bfloat16 *oh, *ol, *wh, *wl;
        cudaGetSymbolAddress((void**)&oh, g_oh);
        cudaGetSymbolAddress((void**)&ol, g_ol);
        cudaGetSymbolAddress((void**)&wh, g_wot_h);
        cudaGetSymbolAddress((void**)&wl, g_wot_l);
        gemm_mma_kernel<DI, 1><<<dim3(DIMM / 128, BB * NN / 128), 256, GEMM_SMEM>>>(
            oh, ol, wh, wl, nullptr, out);
    }
}